// round 15
// baseline (speedup 1.0000x reference)
#include <cuda_runtime.h>
#include <cuda_bf16.h>
#include <cuda_fp16.h>
#include <math.h>
#include <stdint.h>

#define D_MODEL 1024
#define HEADS 16
#define HD 64
#define BATCH 2
#define SEQ 2048
#define BL (BATCH * SEQ)      /* 4096 */
#define D3 (3 * D_MODEL)      /* 3072 */
#define NROWS (BATCH * HEADS * SEQ)

typedef __nv_bfloat16 bf16;

// ---------------------------------------------------------------------------
// Scratch (allocation-free: __device__ globals)
// ---------------------------------------------------------------------------
__device__ __half g_x16[(size_t)BL * D_MODEL];
__device__ __half g_wq16[(size_t)D3 * D_MODEL];
__device__ __half g_wh16[(size_t)D_MODEL * D_MODEL];
__device__ __half g_q16[(size_t)BL * D3];        // QKV fp16
__device__ __half g_ao16h[(size_t)BL * D_MODEL]; // attn_out fp16 hi
__device__ __half g_ao16l[(size_t)BL * D_MODEL]; // attn_out fp16 lo
__device__ float g_psum[(size_t)NROWS * 16];
__device__ __half g_e16[(size_t)NROWS * SEQ];    // unnormalized exp, fp16

// ---------------------------------------------------------------------------
// Portable PTX helpers
// ---------------------------------------------------------------------------
__device__ __forceinline__ uint32_t smem_u32(const void* p) {
    uint32_t a;
    asm("{ .reg .u64 t; cvta.to.shared.u64 t, %1; cvt.u32.u64 %0, t; }"
        : "=r"(a) : "l"(p));
    return a;
}
__device__ __forceinline__ void cp_async16(uint32_t s, const void* g) {
    asm volatile("cp.async.cg.shared.global [%0], [%1], 16;" :: "r"(s), "l"(g));
}
#define CP_COMMIT() asm volatile("cp.async.commit_group;" ::: "memory")
#define CP_WAIT(n)  asm volatile("cp.async.wait_group %0;" :: "n"(n) : "memory")

__device__ __forceinline__ void ldm_x4(uint32_t addr, uint32_t* r) {
    asm volatile("ldmatrix.sync.aligned.m8n8.x4.shared.b16 {%0,%1,%2,%3}, [%4];"
        : "=r"(r[0]), "=r"(r[1]), "=r"(r[2]), "=r"(r[3]) : "r"(addr));
}
__device__ __forceinline__ void ldm_x4_trans(uint32_t addr, uint32_t* r) {
    asm volatile("ldmatrix.sync.aligned.m8n8.x4.trans.shared.b16 {%0,%1,%2,%3}, [%4];"
        : "=r"(r[0]), "=r"(r[1]), "=r"(r[2]), "=r"(r[3]) : "r"(addr));
}
__device__ __forceinline__ void mma_f16(float* c, const uint32_t* a, const uint32_t* b) {
    asm volatile(
        "mma.sync.aligned.m16n8k16.row.col.f32.f16.f16.f32 "
        "{%0,%1,%2,%3}, {%4,%5,%6,%7}, {%8,%9}, {%0,%1,%2,%3};"
        : "+f"(c[0]), "+f"(c[1]), "+f"(c[2]), "+f"(c[3])
        : "r"(a[0]), "r"(a[1]), "r"(a[2]), "r"(a[3]), "r"(b[0]), "r"(b[1]));
}
__device__ __forceinline__ void stg_cs_f4(float* p, float4 v) {
    asm volatile("st.global.cs.v4.f32 [%0], {%1,%2,%3,%4};"
        :: "l"(p), "f"(v.x), "f"(v.y), "f"(v.z), "f"(v.w) : "memory");
}
__device__ __forceinline__ void stg_cs_f2(float* p, float2 v) {
    asm volatile("st.global.cs.v2.f32 [%0], {%1,%2};"
        :: "l"(p), "f"(v.x), "f"(v.y) : "memory");
}
__device__ __forceinline__ void split_store2_h(__half* hi, __half* lo, size_t idx,
                                               float a, float b) {
    __half ha = __float2half_rn(a), hb = __float2half_rn(b);
    __half la = __float2half_rn(a - __half2float(ha));
    __half lb = __float2half_rn(b - __half2float(hb));
    __half2 hv; hv.x = ha; hv.y = hb;
    __half2 lv; lv.x = la; lv.y = lb;
    *(__half2*)(hi + idx) = hv;
    *(__half2*)(lo + idx) = lv;
}
__device__ __forceinline__ float fexp(float x) {
    float t = x * 1.4426950408889634f;
    t = fmaxf(t, -126.0f);
    float n = rintf(t);
    float f = t - n;
    float p = 1.5403530e-4f;
    p = fmaf(p, f, 1.3333558e-3f);
    p = fmaf(p, f, 9.6181291e-3f);
    p = fmaf(p, f, 5.5504109e-2f);
    p = fmaf(p, f, 2.4022651e-1f);
    p = fmaf(p, f, 6.9314718e-1f);
    p = fmaf(p, f, 1.0f);
    return p * __int_as_float(((int)n + 127) << 23);
}

// ---------------------------------------------------------------------------
// Fused conversion kernel: segment 0 rounds x -> fp16; segments 1/2 transpose
// W_qkv / W_h into fp16 [N,K].
//   blocks [0, 4096)           : x round      (4096 * 256 * 4 elems)
//   blocks [4096, 4096+3072)   : W_qkv transpose (96 x 32 tiles)
//   blocks [7168, 7168+1024)   : W_h  transpose (32 x 32 tiles)
// ---------------------------------------------------------------------------
__global__ __launch_bounds__(256) void convert_all_kernel(
    const float* __restrict__ x, __half* __restrict__ x16,
    const float* __restrict__ Wq, __half* __restrict__ wq16,
    const float* __restrict__ Wh, __half* __restrict__ wh16)
{
    const int bx = blockIdx.x;
    if (bx < 4096) {
        int i = bx * 256 + threadIdx.x;
        float4 v = ((const float4*)x)[i];
        __half h[4];
        h[0] = __float2half_rn(v.x);
        h[1] = __float2half_rn(v.y);
        h[2] = __float2half_rn(v.z);
        h[3] = __float2half_rn(v.w);
        ((uint2*)x16)[i] = *(uint2*)h;
        return;
    }
    __shared__ float tile[32][33];
    const float* W;
    __half* O;
    int nx, ky, K, N;
    if (bx < 4096 + 3072) {
        int id = bx - 4096;
        W = Wq; O = wq16; K = D_MODEL; N = D3;
        nx = (id % 96) * 32; ky = (id / 96) * 32;
    } else {
        int id = bx - 7168;
        W = Wh; O = wh16; K = D_MODEL; N = D_MODEL;
        nx = (id % 32) * 32; ky = (id / 32) * 32;
    }
    const int tx = threadIdx.x & 31;
    const int ty = threadIdx.x >> 5;
    #pragma unroll
    for (int i = 0; i < 4; i++)
        tile[ty + 8 * i][tx] = W[(size_t)(ky + ty + 8 * i) * N + nx + tx];
    __syncthreads();
    #pragma unroll
    for (int i = 0; i < 4; i++) {
        float v = tile[tx][ty + 8 * i];
        O[(size_t)(nx + ty + 8 * i) * K + ky + tx] = __float2half_rn(v);
    }
}

// ---------------------------------------------------------------------------
// fp16 1-term QKV GEMM: C = A @ B^T, fp16 out. BK=64, 3-stage pipeline.
// ---------------------------------------------------------------------------
#define QBK 64
#define QGP 72
#define QT_ELEMS (128 * QGP)
#define QS_ELEMS (2 * QT_ELEMS)
#define SMEM_QKV (3 * QS_ELEMS * 2)

__global__ __launch_bounds__(256, 2) void qkv_gemm_f16_kernel(
    const __half* __restrict__ A, const __half* __restrict__ B,
    __half* __restrict__ C, int M, int N, int K)
{
    extern __shared__ __half smq[];
    const uint32_t sbase = smem_u32(smq);
    const int t = threadIdx.x;
    const int warp = t >> 5, lane = t & 31;
    const int bm = blockIdx.y * 128;
    const int bn = blockIdx.x * 128;
    const int wm = (warp >> 1) * 32;
    const int wn = (warp & 1) * 64;

    const __half* srcs[2] = { A, B };

    auto load_stage = [&](int buf, int k0) {
        uint32_t sdst = sbase + (uint32_t)buf * QS_ELEMS * 2;
        #pragma unroll
        for (int m = 0; m < 2; m++) {
            const int rbase = (m == 0) ? bm : bn;
            const __half* S = srcs[m] + (size_t)rbase * K + k0;
            uint32_t td = sdst + (uint32_t)m * QT_ELEMS * 2;
            #pragma unroll
            for (int i = 0; i < 4; i++) {
                int id = t + i * 256;
                int row = id >> 3, c = id & 7;
                cp_async16(td + (uint32_t)(row * QGP + c * 8) * 2,
                           S + (size_t)row * K + c * 8);
            }
        }
        CP_COMMIT();
    };

    float acc[2][8][4];
    #pragma unroll
    for (int mi = 0; mi < 2; mi++)
        #pragma unroll
        for (int nj = 0; nj < 8; nj++)
            #pragma unroll
            for (int e = 0; e < 4; e++) acc[mi][nj][e] = 0.0f;

    const int nch = K >> 6;
    load_stage(0, 0);
    load_stage(1, QBK);

    const int a_r = (lane & 7) + ((lane >> 3) & 1) * 8;
    const int a_c = (lane >> 4) * 8;
    const int b_r = (lane & 7) + (lane >> 4) * 8;
    const int b_c = ((lane >> 3) & 1) * 8;

    int buf = 0;
    for (int c = 0; c < nch; c++) {
        CP_WAIT(1);
        __syncthreads();

        const uint32_t stg = sbase + (uint32_t)buf * QS_ELEMS * 2;
        const uint32_t tA = stg;
        const uint32_t tB = stg + QT_ELEMS * 2;

        #pragma unroll
        for (int ks = 0; ks < QBK; ks += 16) {
            uint32_t ah[2][4], bh[16];
            #pragma unroll
            for (int mi = 0; mi < 2; mi++) {
                uint32_t off = (uint32_t)((wm + mi * 16 + a_r) * QGP + ks + a_c) * 2;
                ldm_x4(tA + off, ah[mi]);
            }
            #pragma unroll
            for (int nj2 = 0; nj2 < 4; nj2++) {
                uint32_t off = (uint32_t)((wn + nj2 * 16 + b_r) * QGP + ks + b_c) * 2;
                ldm_x4(tB + off, bh + nj2 * 4);
            }
            #pragma unroll
            for (int mi = 0; mi < 2; mi++)
                #pragma unroll
                for (int nj = 0; nj < 8; nj++)
                    mma_f16(acc[mi][nj], ah[mi], bh + nj * 2);
        }
        __syncthreads();
        if (c + 2 < nch) {
            int nb = buf + 2;
            if (nb >= 3) nb -= 3;
            load_stage(nb, (c + 2) * QBK);
        } else {
            CP_COMMIT();
        }
        buf = (buf + 1 == 3) ? 0 : buf + 1;
    }

    const int group = lane >> 2, tid4 = lane & 3;
    #pragma unroll
    for (int mi = 0; mi < 2; mi++) {
        int r0 = bm + wm + mi * 16 + group;
        #pragma unroll
        for (int nj = 0; nj < 8; nj++) {
            int cc = bn + wn + nj * 8 + tid4 * 2;
            __half2 v0; v0.x = __float2half_rn(acc[mi][nj][0]);
            v0.y = __float2half_rn(acc[mi][nj][1]);
            __half2 v1; v1.x = __float2half_rn(acc[mi][nj][2]);
            v1.y = __float2half_rn(acc[mi][nj][3]);
            *(__half2*)(C + (size_t)r0 * N + cc) = v0;
            *(__half2*)(C + (size_t)(r0 + 8) * N + cc) = v1;
        }
    }
}

// ---------------------------------------------------------------------------
// fp16 2-term out-proj GEMM: C = (Ahi+Alo) @ B^T + bias (streaming stores).
// ---------------------------------------------------------------------------
#define BK 32
#define GP 40
#define GT_ELEMS (128 * GP)
#define OS_ELEMS (3 * GT_ELEMS)
#define SMEM_OP (2 * OS_ELEMS * 2)

__global__ __launch_bounds__(256, 2) void outproj_gemm_f16_kernel(
    const __half* __restrict__ Ahi, const __half* __restrict__ Alo,
    const __half* __restrict__ B, float* __restrict__ C,
    const float* __restrict__ bias, int M, int N, int K)
{
    extern __shared__ __half smq[];
    const uint32_t sbase = smem_u32(smq);
    const int t = threadIdx.x;
    const int warp = t >> 5, lane = t & 31;
    const int bm = blockIdx.y * 128;
    const int bn = blockIdx.x * 128;
    const int wm = (warp >> 1) * 32;
    const int wn = (warp & 1) * 64;

    const __half* srcs[3] = { Ahi, Alo, B };

    auto load_stage = [&](int buf, int k0) {
        uint32_t sdst = sbase + (uint32_t)buf * OS_ELEMS * 2;
        #pragma unroll
        for (int m = 0; m < 3; m++) {
            const int rbase = (m < 2) ? bm : bn;
            const __half* S = srcs[m] + (size_t)rbase * K + k0;
            uint32_t td = sdst + (uint32_t)m * GT_ELEMS * 2;
            #pragma unroll
            for (int i = 0; i < 2; i++) {
                int id = t + i * 256;
                int row = id >> 2, c = id & 3;
                cp_async16(td + (uint32_t)(row * GP + c * 8) * 2,
                           S + (size_t)row * K + c * 8);
            }
        }
        CP_COMMIT();
    };

    float acc[2][8][4];
    #pragma unroll
    for (int mi = 0; mi < 2; mi++)
        #pragma unroll
        for (int nj = 0; nj < 8; nj++)
            #pragma unroll
            for (int e = 0; e < 4; e++) acc[mi][nj][e] = 0.0f;

    const int nch = K >> 5;
    load_stage(0, 0);
    load_stage(1, BK);

    const int a_r = (lane & 7) + ((lane >> 3) & 1) * 8;
    const int a_c = (lane >> 4) * 8;
    const int b_r = (lane & 7) + (lane >> 4) * 8;
    const int b_c = ((lane >> 3) & 1) * 8;

    for (int c = 0; c < nch; c++) {
        if (c < nch - 1) { CP_WAIT(1); } else { CP_WAIT(0); }
        __syncthreads();

        const uint32_t stg = sbase + (uint32_t)(c & 1) * OS_ELEMS * 2;
        const uint32_t tAhi = stg;
        const uint32_t tAlo = stg + GT_ELEMS * 2;
        const uint32_t tB = stg + 2 * GT_ELEMS * 2;

        #pragma unroll
        for (int ks = 0; ks < BK; ks += 16) {
            uint32_t ah[2][4], al[2][4], bh[16];
            #pragma unroll
            for (int mi = 0; mi < 2; mi++) {
                uint32_t off = (uint32_t)((wm + mi * 16 + a_r) * GP + ks + a_c) * 2;
                ldm_x4(tAhi + off, ah[mi]);
                ldm_x4(tAlo + off, al[mi]);
            }
            #pragma unroll
            for (int nj2 = 0; nj2 < 4; nj2++) {
                uint32_t off = (uint32_t)((wn + nj2 * 16 + b_r) * GP + ks + b_c) * 2;
                ldm_x4(tB + off, bh + nj2 * 4);
            }
            #pragma unroll
            for (int mi = 0; mi < 2; mi++)
                #pragma unroll
                for (int nj = 0; nj < 8; nj++) {
                    mma_f16(acc[mi][nj], ah[mi], bh + nj * 2);
                    mma_f16(acc[mi][nj], al[mi], bh + nj * 2);
                }
        }
        __syncthreads();
        if (c + 2 < nch) load_stage(c & 1, (c + 2) * BK);
    }

    const int group = lane >> 2, tid4 = lane & 3;
    #pragma unroll
    for (int mi = 0; mi < 2; mi++) {
        int r0 = bm + wm + mi * 16 + group;
        #pragma unroll
        for (int nj = 0; nj < 8; nj++) {
            int cc = bn + wn + nj * 8 + tid4 * 2;
            float2 bb = *(const float2*)(bias + cc);
            stg_cs_f2(C + (size_t)r0 * N + cc,
                      make_float2(acc[mi][nj][0] + bb.x, acc[mi][nj][1] + bb.y));
            stg_cs_f2(C + (size_t)(r0 + 8) * N + cc,
                      make_float2(acc[mi][nj][2] + bb.x, acc[mi][nj][3] + bb.y));
        }
    }
}

// ---------------------------------------------------------------------------
// Scores via fp16 HMMA 1-term (R11-proven).
// ---------------------------------------------------------------------------
#define SP 72
#define ST_ELEMS (128 * SP)
#define SMEM_SCORES (2 * ST_ELEMS * 2)

__global__ __launch_bounds__(256, 2) void scores_mma_kernel(
    const float* __restrict__ mask, __half* __restrict__ e16,
    const __half* __restrict__ q16, float* __restrict__ psum)
{
    extern __shared__ __half smh[];
    const uint32_t sbase = smem_u32(smh);
    const int t = threadIdx.x;
    const int warp = t >> 5, lane = t & 31;
    const int bh = blockIdx.z;
    const int b = bh / HEADS, h = bh % HEADS;
    const int bm = blockIdx.y * 128;
    const int bn = blockIdx.x * 128;
    const int wm = (warp >> 1) * 32;
    const int wn = (warp & 1) * 64;

    const __half* bases[2] = {
        q16 + ((size_t)(b * SEQ + bm)) * D3 + h * HD,
        q16 + ((size_t)(b * SEQ + bn)) * D3 + D_MODEL + h * HD };
    #pragma unroll
    for (int m = 0; m < 2; m++) {
        uint32_t td = sbase + (uint32_t)m * ST_ELEMS * 2;
        #pragma unroll
        for (int i = 0; i < 4; i++) {
            int id = t + i * 256;
            int r = id >> 3, c = id & 7;
            cp_async16(td + (uint32_t)(r * SP + c * 8) * 2,
                       bases[m] + (size_t)r * D3 + c * 8);
        }
    }
    CP_COMMIT();

    float acc[2][8][4];
    #pragma unroll
    for (int mi = 0; mi < 2; mi++)
        #pragma unroll
        for (int nj = 0; nj < 8; nj++)
            #pragma unroll
            for (int e = 0; e < 4; e++) acc[mi][nj][e] = 0.0f;

    const int a_r = (lane & 7) + ((lane >> 3) & 1) * 8;
    const int a_c = (lane >> 4) * 8;
    const int b_r = (lane & 7) + (lane >> 4) * 8;
    const int b_c = ((lane >> 3) & 1) * 8;

    const uint32_t tQ = sbase;
    const uint32_t tK = sbase + ST_ELEMS * 2;

    CP_WAIT(0);
    __syncthreads();

    #pragma unroll
    for (int ks = 0; ks < 4; ks++) {
        uint32_t ah[2][4], bhf[16];
        #pragma unroll
        for (int mi = 0; mi < 2; mi++) {
            uint32_t off = (uint32_t)((wm + mi * 16 + a_r) * SP + ks * 16 + a_c) * 2;
            ldm_x4(tQ + off, ah[mi]);
        }
        #pragma unroll
        for (int nj2 = 0; nj2 < 4; nj2++) {
            uint32_t off = (uint32_t)((wn + nj2 * 16 + b_r) * SP + ks * 16 + b_c) * 2;
            ldm_x4(tK + off, bhf + nj2 * 4);
        }
        #pragma unroll
        for (int mi = 0; mi < 2; mi++)
            #pragma unroll
            for (int nj = 0; nj < 8; nj++)
                mma_f16(acc[mi][nj], ah[mi], bhf + nj * 2);
    }

    const int group = lane >> 2, tid4 = lane & 3;
    float mq[4];
    #pragma unroll
    for (int mi = 0; mi < 2; mi++) {
        mq[mi * 2 + 0] = mask[b * SEQ + bm + wm + mi * 16 + group];
        mq[mi * 2 + 1] = mask[b * SEQ + bm + wm + mi * 16 + group + 8];
    }
    __half* out = e16 + (size_t)bh * SEQ * SEQ;
    float srow[2][2];
    srow[0][0] = srow[0][1] = srow[1][0] = srow[1][1] = 0.0f;
    #pragma unroll
    for (int nj = 0; nj < 8; nj++) {
        int cc = bn + wn + nj * 8 + tid4 * 2;
        float2 mk = *(const float2*)(mask + b * SEQ + cc);
        #pragma unroll
        for (int mi = 0; mi < 2; mi++) {
            int r0 = bm + wm + mi * 16 + group;
            float v0 = acc[mi][nj][0], v1 = acc[mi][nj][1];
            float v2 = acc[mi][nj][2], v3 = acc[mi][nj][3];
            if (mq[mi * 2 + 0] * mk.x == 0.0f) v0 = -100000.0f;
            if (mq[mi * 2 + 0] * mk.y == 0.0f) v1 = -100000.0f;
            if (mq[mi * 2 + 1] * mk.x == 0.0f) v2 = -100000.0f;
            if (mq[mi * 2 + 1] * mk.y == 0.0f) v3 = -100000.0f;
            __half h0 = __float2half_rn(fmaxf(fexp(v0 * 0.03125f), 1e-7f));
            __half h1 = __float2half_rn(fmaxf(fexp(v1 * 0.03125f), 1e-7f));
            __half h2 = __float2half_rn(fmaxf(fexp(v2 * 0.03125f), 1e-7f));
            __half h3 = __float2half_rn(fmaxf(fexp(v3 * 0.03125f), 1e-7f));
            __half2 p01; p01.x = h0; p01.y = h1;
            __half2 p23; p23.x = h2; p23.y = h3;
            *(__half2*)(out + (size_t)r0 * SEQ + cc) = p01;
            *(__half2*)(out + (size_t)(r0 + 8) * SEQ + cc) = p23;
            srow[mi][0] += __half2float(h0) + __half2float(h1);
            srow[mi][1] += __half2float(h2) + __half2float(h3);
        }
    }
    #pragma unroll
    for (int mi = 0; mi < 2; mi++) {
        #pragma unroll
        for (int s = 0; s < 2; s++) {
            srow[mi][s] += __shfl_xor_sync(0xffffffffu, srow[mi][s], 1);
            srow[mi][s] += __shfl_xor_sync(0xffffffffu, srow[mi][s], 2);
        }
    }
    __syncthreads();
    float* rs = (float*)smh;
    if (tid4 == 0) {
        #pragma unroll
        for (int mi = 0; mi < 2; mi++) {
            rs[(wm + mi * 16 + group) * 2 + (warp & 1)] = srow[mi][0];
            rs[(wm + mi * 16 + group + 8) * 2 + (warp & 1)] = srow[mi][1];
        }
    }
    __syncthreads();
    if (t < 128)
        psum[((size_t)bh * SEQ + bm + t) * 16 + blockIdx.x] = rs[t * 2] + rs[t * 2 + 1];
}

// ---------------------------------------------------------------------------
// av with fused row-sum inverse; streaming stores for the attn fp32 output.
// ---------------------------------------------------------------------------
#define EP 72
#define AVE(i) ((i) * 18432)
#define AVV(i) (36864 + (i) * 9216)
#define AVINV  55296
#define SMEM_AV (55296 + 512)

__global__ __launch_bounds__(256, 2) void av_mma_kernel(
    const __half* __restrict__ e16, float* __restrict__ attn,
    const __half* __restrict__ q16,
    __half* __restrict__ aohi, __half* __restrict__ aolo,
    const float* __restrict__ psum)
{
    extern __shared__ char smc[];
    const uint32_t sbase = smem_u32(smc);
    const int t = threadIdx.x;
    const int warp = t >> 5, lane = t & 31;
    const int bh = blockIdx.y;
    const int b = bh / HEADS, h = bh % HEADS;
    const int bm = blockIdx.x * 128;
    const int wm = warp * 16;

    const __half* Ebase = e16 + (size_t)bh * SEQ * SEQ + (size_t)bm * SEQ;
    float* Abase = attn + (size_t)bh * SEQ * SEQ + (size_t)bm * SEQ;
    const __half* V = q16 + (size_t)b * SEQ * D3 + 2 * D_MODEL + h * HD;

    float* inv_s = (float*)(smc + AVINV);
    if (t < 128) {
        const float* p = psum + ((size_t)bh * SEQ + bm + t) * 16;
        float4 a = *(const float4*)(p);
        float4 b2 = *(const float4*)(p + 4);
        float4 cc = *(const float4*)(p + 8);
        float4 d = *(const float4*)(p + 12);
        float s = a.x + a.y + a.z + a.w + b2.x + b2.y + b2.z + b2.w
                + cc.x + cc.y + cc.z + cc.w + d.x + d.y + d.z + d.w;
        inv_s[t] = 1.0f / s;
    }
    __syncthreads();

    auto load_chunk = [&](int c) {
        const int k0 = c * 64;
        const uint32_t buf = c & 1;
        #pragma unroll
        for (int i = 0; i < 4; i++) {
            int id = t + i * 256;
            int r = id >> 3, cs = id & 7;
            cp_async16(sbase + AVE(buf) + (uint32_t)(r * EP + cs * 8) * 2,
                       Ebase + (size_t)r * SEQ + k0 + cs * 8);
        }
        #pragma unroll
        for (int i = 0; i < 2; i++) {
            int id = t + i * 256;
            int r = id >> 3, cs = id & 7;
            cp_async16(sbase + AVV(buf) + (uint32_t)(r * EP + cs * 8) * 2,
                       V + (size_t)(k0 + r) * D3 + cs * 8);
        }
        CP_COMMIT();
    };

    float acc[8][4];
    #pragma unroll
    for (int nj = 0; nj < 8; nj++)
        #pragma unroll
        for (int e = 0; e < 4; e++) acc[nj][e] = 0.0f;

    load_chunk(0);

    const int a_r = (lane & 7) + ((lane >> 3) & 1) * 8;
    const int a_c = (lane >> 4) * 8;
    const int tb_r = lane & 15;
    const int tb_c = (lane >> 4) * 8;

    for (int c = 0; c < SEQ / 64; c++) {
        CP_WAIT(0);
        __syncthreads();
        const int k0 = c * 64;
        const uint32_t buf = c & 1;
        if (c + 1 < SEQ / 64) load_chunk(c + 1);

        const __half* Es = (const __half*)(smc + AVE(buf));
        #pragma unroll
        for (int i = 0; i < 8; i++) {
            int id = t + i * 256;
            int r = id >> 4, c4 = id & 15;
            uint2 raw = *(const uint2*)(Es + r * EP + c4 * 4);
            __half2 p01 = *(__half2*)&raw.x;
            __half2 p23 = *(__half2*)&raw.y;
            float s = inv_s[r];
            float4 o;
            o.x = __half2float(p01.x) * s;
            o.y = __half2float(p01.y) * s;
            o.z = __half2float(p23.x) * s;
            o.w = __half2float(p23.y) * s;
            stg_cs_f4(Abase + (size_t)r * SEQ + k0 + c4 * 4, o);
        }

        const uint32_t tA = sbase + AVE(buf);
        const uint32_t tV = sbase + AVV(buf);
        #pragma unroll
        for (int ks = 0; ks < 4; ks++) {
            uint32_t ah[4], bhf[16];
            uint32_t aoff = (uint32_t)((wm + a_r) * EP + ks * 16 + a_c) * 2;
            ldm_x4(tA + aoff, ah);
            #pragma unroll
            for (int nj2 = 0; nj2 < 4; nj2++) {
                uint32_t boff =
                    (uint32_t)((ks * 16 + tb_r) * EP + nj2 * 16 + tb_c) * 2;
                ldm_x4_trans(tV + boff, bhf + nj2 * 4);
            }
            #pragma unroll
            for (int nj = 0; nj < 8; nj++)
                mma_f16(acc[nj], ah, bhf + nj * 2);
        }
    }

    const int group = lane >> 2, tid4 = lane & 3;
    const float ia = inv_s[wm + group];
    const float ib = inv_s[wm + group + 8];
    #pragma unroll
    for (int nj = 0; nj < 8; nj++) {
        int cc = h * HD + nj * 8 + tid4 * 2;
        size_t r0 = (size_t)(b * SEQ + bm + wm + group) * D_MODEL + cc;
        size_t r1 = r0 + (size_t)8 * D_MODEL;
        split_store2_h(aohi, aolo, r0, acc[nj][0] * ia, acc[nj][1] * ia);
        split_store2_h(aohi, aolo, r1, acc[nj][2] * ib, acc[nj][3] * ib);
    }
}

// ---------------------------------------------------------------------------
extern "C" void kernel_launch(void* const* d_in, const int* in_sizes, int n_in,
                              void* d_out, int out_size)
{
    const float* x     = (const float*)d_in[0];
    const float* mask  = (const float*)d_in[1];
    const float* W_qkv = (const float*)d_in[2];
    const float* W_h   = (const float*)d_in[3];
    const float* b_h   = (const float*)d_in[4];

    float* out  = (float*)d_out;
    float* attn = out + (size_t)BL * D_MODEL;

    __half *x16, *wq16, *wh16, *q16, *e16, *aohi, *aolo;
    float *psum;
    cudaGetSymbolAddress((void**)&x16, g_x16);
    cudaGetSymbolAddress((void**)&wq16, g_wq16);
    cudaGetSymbolAddress((void**)&wh16, g_wh16);
    cudaGetSymbolAddress((void**)&q16, g_q16);
    cudaGetSymbolAddress((void**)&aohi, g_ao16h);
    cudaGetSymbolAddress((void**)&aolo, g_ao16l);
    cudaGetSymbolAddress((void**)&psum, g_psum);
    cudaGetSymbolAddress((void**)&e16, g_e16);

    cudaFuncSetAttribute(qkv_gemm_f16_kernel, cudaFuncAttributeMaxDynamicSharedMemorySize, SMEM_QKV);
    cudaFuncSetAttribute(outproj_gemm_f16_kernel, cudaFuncAttributeMaxDynamicSharedMemorySize, SMEM_OP);
    cudaFuncSetAttribute(scores_mma_kernel, cudaFuncAttributeMaxDynamicSharedMemorySize, SMEM_SCORES);
    cudaFuncSetAttribute(av_mma_kernel, cudaFuncAttributeMaxDynamicSharedMemorySize, SMEM_AV);

    // 0) fused input conversions (x round + both W transposes)
    convert_all_kernel<<<4096 + 3072 + 1024, 256>>>(x, x16, W_qkv, wq16, W_h, wh16);

    // 1) QKV = x @ W_qkv (fp16 1-term, BK=64, 3-stage) -> fp16
    qkv_gemm_f16_kernel<<<dim3(D3 / 128, BL / 128), 256, SMEM_QKV>>>(
        x16, wq16, q16, BL, D3, D_MODEL);

    // 2) scores (fp16 1-term) + fused exp -> fp16 scratch + psums
    scores_mma_kernel<<<dim3(SEQ / 128, SEQ / 128, BATCH * HEADS), 256, SMEM_SCORES>>>(
        mask, e16, q16, psum);

    // 3) attn @ V (fused rowinv, 1-term fp16) + streaming attn fp32 write
    av_mma_kernel<<<dim3(SEQ / 128, BATCH * HEADS), 256, SMEM_AV>>>(
        e16, attn, q16, aohi, aolo, psum);

    // 4) output = ao @ W_h + b_h (fp16 2-term, streaming out write)
    outproj_gemm_f16_kernel<<<dim3(D_MODEL / 128, BL / 128), 256, SMEM_OP>>>(
        aohi, aolo, wh16, out, b_h, BL, D_MODEL, D_MODEL);
}

// round 16
// speedup vs baseline: 1.0175x; 1.0175x over previous
#include <cuda_runtime.h>
#include <cuda_bf16.h>
#include <cuda_fp16.h>
#include <math.h>
#include <stdint.h>

#define D_MODEL 1024
#define HEADS 16
#define HD 64
#define BATCH 2
#define SEQ 2048
#define BL (BATCH * SEQ)      /* 4096 */
#define D3 (3 * D_MODEL)      /* 3072 */
#define NROWS (BATCH * HEADS * SEQ)

typedef __nv_bfloat16 bf16;

// ---------------------------------------------------------------------------
// Scratch (allocation-free: __device__ globals)
// ---------------------------------------------------------------------------
__device__ __half g_x16[(size_t)BL * D_MODEL];
__device__ __half g_wq16[(size_t)D3 * D_MODEL];
__device__ __half g_wh16[(size_t)D_MODEL * D_MODEL];
__device__ __half g_q16[(size_t)BL * D3];        // QKV fp16
__device__ __half g_ao16h[(size_t)BL * D_MODEL]; // attn_out fp16 hi
__device__ __half g_ao16l[(size_t)BL * D_MODEL]; // attn_out fp16 lo
__device__ float g_psum[(size_t)NROWS * 16];
__device__ __half g_e16[(size_t)NROWS * SEQ];    // unnormalized exp, fp16

// ---------------------------------------------------------------------------
// Portable PTX helpers
// ---------------------------------------------------------------------------
__device__ __forceinline__ uint32_t smem_u32(const void* p) {
    uint32_t a;
    asm("{ .reg .u64 t; cvta.to.shared.u64 t, %1; cvt.u32.u64 %0, t; }"
        : "=r"(a) : "l"(p));
    return a;
}
__device__ __forceinline__ void cp_async16(uint32_t s, const void* g) {
    asm volatile("cp.async.cg.shared.global [%0], [%1], 16;" :: "r"(s), "l"(g));
}
#define CP_COMMIT() asm volatile("cp.async.commit_group;" ::: "memory")
#define CP_WAIT(n)  asm volatile("cp.async.wait_group %0;" :: "n"(n) : "memory")

__device__ __forceinline__ void ldm_x4(uint32_t addr, uint32_t* r) {
    asm volatile("ldmatrix.sync.aligned.m8n8.x4.shared.b16 {%0,%1,%2,%3}, [%4];"
        : "=r"(r[0]), "=r"(r[1]), "=r"(r[2]), "=r"(r[3]) : "r"(addr));
}
__device__ __forceinline__ void ldm_x4_trans(uint32_t addr, uint32_t* r) {
    asm volatile("ldmatrix.sync.aligned.m8n8.x4.trans.shared.b16 {%0,%1,%2,%3}, [%4];"
        : "=r"(r[0]), "=r"(r[1]), "=r"(r[2]), "=r"(r[3]) : "r"(addr));
}
__device__ __forceinline__ void mma_f16(float* c, const uint32_t* a, const uint32_t* b) {
    asm volatile(
        "mma.sync.aligned.m16n8k16.row.col.f32.f16.f16.f32 "
        "{%0,%1,%2,%3}, {%4,%5,%6,%7}, {%8,%9}, {%0,%1,%2,%3};"
        : "+f"(c[0]), "+f"(c[1]), "+f"(c[2]), "+f"(c[3])
        : "r"(a[0]), "r"(a[1]), "r"(a[2]), "r"(a[3]), "r"(b[0]), "r"(b[1]));
}
__device__ __forceinline__ void split_store2_h(__half* hi, __half* lo, size_t idx,
                                               float a, float b) {
    __half ha = __float2half_rn(a), hb = __float2half_rn(b);
    __half la = __float2half_rn(a - __half2float(ha));
    __half lb = __float2half_rn(b - __half2float(hb));
    __half2 hv; hv.x = ha; hv.y = hb;
    __half2 lv; lv.x = la; lv.y = lb;
    *(__half2*)(hi + idx) = hv;
    *(__half2*)(lo + idx) = lv;
}
__device__ __forceinline__ float fexp(float x) {
    float t = x * 1.4426950408889634f;
    t = fmaxf(t, -126.0f);
    float n = rintf(t);
    float f = t - n;
    float p = 1.5403530e-4f;
    p = fmaf(p, f, 1.3333558e-3f);
    p = fmaf(p, f, 9.6181291e-3f);
    p = fmaf(p, f, 5.5504109e-2f);
    p = fmaf(p, f, 2.4022651e-1f);
    p = fmaf(p, f, 6.9314718e-1f);
    p = fmaf(p, f, 1.0f);
    return p * __int_as_float(((int)n + 127) << 23);
}

// ---------------------------------------------------------------------------
// Fused conversion kernel (R15-proven layout).
// ---------------------------------------------------------------------------
__global__ __launch_bounds__(256) void convert_all_kernel(
    const float* __restrict__ x, __half* __restrict__ x16,
    const float* __restrict__ Wq, __half* __restrict__ wq16,
    const float* __restrict__ Wh, __half* __restrict__ wh16)
{
    const int bx = blockIdx.x;
    if (bx < 4096) {
        int i = bx * 256 + threadIdx.x;
        float4 v = ((const float4*)x)[i];
        __half h[4];
        h[0] = __float2half_rn(v.x);
        h[1] = __float2half_rn(v.y);
        h[2] = __float2half_rn(v.z);
        h[3] = __float2half_rn(v.w);
        ((uint2*)x16)[i] = *(uint2*)h;
        return;
    }
    __shared__ float tile[32][33];
    const float* W;
    __half* O;
    int nx, ky, K, N;
    if (bx < 4096 + 3072) {
        int id = bx - 4096;
        W = Wq; O = wq16; K = D_MODEL; N = D3;
        nx = (id % 96) * 32; ky = (id / 96) * 32;
    } else {
        int id = bx - 7168;
        W = Wh; O = wh16; K = D_MODEL; N = D_MODEL;
        nx = (id % 32) * 32; ky = (id / 32) * 32;
    }
    const int tx = threadIdx.x & 31;
    const int ty = threadIdx.x >> 5;
    #pragma unroll
    for (int i = 0; i < 4; i++)
        tile[ty + 8 * i][tx] = W[(size_t)(ky + ty + 8 * i) * N + nx + tx];
    __syncthreads();
    #pragma unroll
    for (int i = 0; i < 4; i++) {
        float v = tile[tx][ty + 8 * i];
        O[(size_t)(nx + ty + 8 * i) * K + ky + tx] = __float2half_rn(v);
    }
}

// ---------------------------------------------------------------------------
// fp16 1-term QKV GEMM: C = A @ B^T, fp16 out. BK=64, 3-stage pipeline.
// ---------------------------------------------------------------------------
#define QBK 64
#define QGP 72
#define QT_ELEMS (128 * QGP)
#define QS_ELEMS (2 * QT_ELEMS)
#define SMEM_QKV (3 * QS_ELEMS * 2)

__global__ __launch_bounds__(256, 2) void qkv_gemm_f16_kernel(
    const __half* __restrict__ A, const __half* __restrict__ B,
    __half* __restrict__ C, int M, int N, int K)
{
    extern __shared__ __half smq[];
    const uint32_t sbase = smem_u32(smq);
    const int t = threadIdx.x;
    const int warp = t >> 5, lane = t & 31;
    const int bm = blockIdx.y * 128;
    const int bn = blockIdx.x * 128;
    const int wm = (warp >> 1) * 32;
    const int wn = (warp & 1) * 64;

    const __half* srcs[2] = { A, B };

    auto load_stage = [&](int buf, int k0) {
        uint32_t sdst = sbase + (uint32_t)buf * QS_ELEMS * 2;
        #pragma unroll
        for (int m = 0; m < 2; m++) {
            const int rbase = (m == 0) ? bm : bn;
            const __half* S = srcs[m] + (size_t)rbase * K + k0;
            uint32_t td = sdst + (uint32_t)m * QT_ELEMS * 2;
            #pragma unroll
            for (int i = 0; i < 4; i++) {
                int id = t + i * 256;
                int row = id >> 3, c = id & 7;
                cp_async16(td + (uint32_t)(row * QGP + c * 8) * 2,
                           S + (size_t)row * K + c * 8);
            }
        }
        CP_COMMIT();
    };

    float acc[2][8][4];
    #pragma unroll
    for (int mi = 0; mi < 2; mi++)
        #pragma unroll
        for (int nj = 0; nj < 8; nj++)
            #pragma unroll
            for (int e = 0; e < 4; e++) acc[mi][nj][e] = 0.0f;

    const int nch = K >> 6;
    load_stage(0, 0);
    load_stage(1, QBK);

    const int a_r = (lane & 7) + ((lane >> 3) & 1) * 8;
    const int a_c = (lane >> 4) * 8;
    const int b_r = (lane & 7) + (lane >> 4) * 8;
    const int b_c = ((lane >> 3) & 1) * 8;

    int buf = 0;
    for (int c = 0; c < nch; c++) {
        CP_WAIT(1);
        __syncthreads();

        const uint32_t stg = sbase + (uint32_t)buf * QS_ELEMS * 2;
        const uint32_t tA = stg;
        const uint32_t tB = stg + QT_ELEMS * 2;

        #pragma unroll
        for (int ks = 0; ks < QBK; ks += 16) {
            uint32_t ah[2][4], bh[16];
            #pragma unroll
            for (int mi = 0; mi < 2; mi++) {
                uint32_t off = (uint32_t)((wm + mi * 16 + a_r) * QGP + ks + a_c) * 2;
                ldm_x4(tA + off, ah[mi]);
            }
            #pragma unroll
            for (int nj2 = 0; nj2 < 4; nj2++) {
                uint32_t off = (uint32_t)((wn + nj2 * 16 + b_r) * QGP + ks + b_c) * 2;
                ldm_x4(tB + off, bh + nj2 * 4);
            }
            #pragma unroll
            for (int mi = 0; mi < 2; mi++)
                #pragma unroll
                for (int nj = 0; nj < 8; nj++)
                    mma_f16(acc[mi][nj], ah[mi], bh + nj * 2);
        }
        __syncthreads();
        if (c + 2 < nch) {
            int nb = buf + 2;
            if (nb >= 3) nb -= 3;
            load_stage(nb, (c + 2) * QBK);
        } else {
            CP_COMMIT();
        }
        buf = (buf + 1 == 3) ? 0 : buf + 1;
    }

    const int group = lane >> 2, tid4 = lane & 3;
    #pragma unroll
    for (int mi = 0; mi < 2; mi++) {
        int r0 = bm + wm + mi * 16 + group;
        #pragma unroll
        for (int nj = 0; nj < 8; nj++) {
            int cc = bn + wn + nj * 8 + tid4 * 2;
            __half2 v0; v0.x = __float2half_rn(acc[mi][nj][0]);
            v0.y = __float2half_rn(acc[mi][nj][1]);
            __half2 v1; v1.x = __float2half_rn(acc[mi][nj][2]);
            v1.y = __float2half_rn(acc[mi][nj][3]);
            *(__half2*)(C + (size_t)r0 * N + cc) = v0;
            *(__half2*)(C + (size_t)(r0 + 8) * N + cc) = v1;
        }
    }
}

// ---------------------------------------------------------------------------
// fp16 2-term out-proj GEMM (R12-proven, plain stores).
// ---------------------------------------------------------------------------
#define BK 32
#define GP 40
#define GT_ELEMS (128 * GP)
#define OS_ELEMS (3 * GT_ELEMS)
#define SMEM_OP (2 * OS_ELEMS * 2)

__global__ __launch_bounds__(256, 2) void outproj_gemm_f16_kernel(
    const __half* __restrict__ Ahi, const __half* __restrict__ Alo,
    const __half* __restrict__ B, float* __restrict__ C,
    const float* __restrict__ bias, int M, int N, int K)
{
    extern __shared__ __half smq[];
    const uint32_t sbase = smem_u32(smq);
    const int t = threadIdx.x;
    const int warp = t >> 5, lane = t & 31;
    const int bm = blockIdx.y * 128;
    const int bn = blockIdx.x * 128;
    const int wm = (warp >> 1) * 32;
    const int wn = (warp & 1) * 64;

    const __half* srcs[3] = { Ahi, Alo, B };

    auto load_stage = [&](int buf, int k0) {
        uint32_t sdst = sbase + (uint32_t)buf * OS_ELEMS * 2;
        #pragma unroll
        for (int m = 0; m < 3; m++) {
            const int rbase = (m < 2) ? bm : bn;
            const __half* S = srcs[m] + (size_t)rbase * K + k0;
            uint32_t td = sdst + (uint32_t)m * GT_ELEMS * 2;
            #pragma unroll
            for (int i = 0; i < 2; i++) {
                int id = t + i * 256;
                int row = id >> 2, c = id & 3;
                cp_async16(td + (uint32_t)(row * GP + c * 8) * 2,
                           S + (size_t)row * K + c * 8);
            }
        }
        CP_COMMIT();
    };

    float acc[2][8][4];
    #pragma unroll
    for (int mi = 0; mi < 2; mi++)
        #pragma unroll
        for (int nj = 0; nj < 8; nj++)
            #pragma unroll
            for (int e = 0; e < 4; e++) acc[mi][nj][e] = 0.0f;

    const int nch = K >> 5;
    load_stage(0, 0);
    load_stage(1, BK);

    const int a_r = (lane & 7) + ((lane >> 3) & 1) * 8;
    const int a_c = (lane >> 4) * 8;
    const int b_r = (lane & 7) + (lane >> 4) * 8;
    const int b_c = ((lane >> 3) & 1) * 8;

    for (int c = 0; c < nch; c++) {
        if (c < nch - 1) { CP_WAIT(1); } else { CP_WAIT(0); }
        __syncthreads();

        const uint32_t stg = sbase + (uint32_t)(c & 1) * OS_ELEMS * 2;
        const uint32_t tAhi = stg;
        const uint32_t tAlo = stg + GT_ELEMS * 2;
        const uint32_t tB = stg + 2 * GT_ELEMS * 2;

        #pragma unroll
        for (int ks = 0; ks < BK; ks += 16) {
            uint32_t ah[2][4], al[2][4], bh[16];
            #pragma unroll
            for (int mi = 0; mi < 2; mi++) {
                uint32_t off = (uint32_t)((wm + mi * 16 + a_r) * GP + ks + a_c) * 2;
                ldm_x4(tAhi + off, ah[mi]);
                ldm_x4(tAlo + off, al[mi]);
            }
            #pragma unroll
            for (int nj2 = 0; nj2 < 4; nj2++) {
                uint32_t off = (uint32_t)((wn + nj2 * 16 + b_r) * GP + ks + b_c) * 2;
                ldm_x4(tB + off, bh + nj2 * 4);
            }
            #pragma unroll
            for (int mi = 0; mi < 2; mi++)
                #pragma unroll
                for (int nj = 0; nj < 8; nj++) {
                    mma_f16(acc[mi][nj], ah[mi], bh + nj * 2);
                    mma_f16(acc[mi][nj], al[mi], bh + nj * 2);
                }
        }
        __syncthreads();
        if (c + 2 < nch) load_stage(c & 1, (c + 2) * BK);
    }

    const int group = lane >> 2, tid4 = lane & 3;
    #pragma unroll
    for (int mi = 0; mi < 2; mi++) {
        int r0 = bm + wm + mi * 16 + group;
        #pragma unroll
        for (int nj = 0; nj < 8; nj++) {
            int cc = bn + wn + nj * 8 + tid4 * 2;
            float2 bb = *(const float2*)(bias + cc);
            *(float2*)(C + (size_t)r0 * N + cc) =
                make_float2(acc[mi][nj][0] + bb.x, acc[mi][nj][1] + bb.y);
            *(float2*)(C + (size_t)(r0 + 8) * N + cc) =
                make_float2(acc[mi][nj][2] + bb.x, acc[mi][nj][3] + bb.y);
        }
    }
}

// ---------------------------------------------------------------------------
// Scores via fp16 HMMA 1-term (R11-proven).
// ---------------------------------------------------------------------------
#define SP 72
#define ST_ELEMS (128 * SP)
#define SMEM_SCORES (2 * ST_ELEMS * 2)

__global__ __launch_bounds__(256, 2) void scores_mma_kernel(
    const float* __restrict__ mask, __half* __restrict__ e16,
    const __half* __restrict__ q16, float* __restrict__ psum)
{
    extern __shared__ __half smh[];
    const uint32_t sbase = smem_u32(smh);
    const int t = threadIdx.x;
    const int warp = t >> 5, lane = t & 31;
    const int bh = blockIdx.z;
    const int b = bh / HEADS, h = bh % HEADS;
    const int bm = blockIdx.y * 128;
    const int bn = blockIdx.x * 128;
    const int wm = (warp >> 1) * 32;
    const int wn = (warp & 1) * 64;

    const __half* bases[2] = {
        q16 + ((size_t)(b * SEQ + bm)) * D3 + h * HD,
        q16 + ((size_t)(b * SEQ + bn)) * D3 + D_MODEL + h * HD };
    #pragma unroll
    for (int m = 0; m < 2; m++) {
        uint32_t td = sbase + (uint32_t)m * ST_ELEMS * 2;
        #pragma unroll
        for (int i = 0; i < 4; i++) {
            int id = t + i * 256;
            int r = id >> 3, c = id & 7;
            cp_async16(td + (uint32_t)(r * SP + c * 8) * 2,
                       bases[m] + (size_t)r * D3 + c * 8);
        }
    }
    CP_COMMIT();

    float acc[2][8][4];
    #pragma unroll
    for (int mi = 0; mi < 2; mi++)
        #pragma unroll
        for (int nj = 0; nj < 8; nj++)
            #pragma unroll
            for (int e = 0; e < 4; e++) acc[mi][nj][e] = 0.0f;

    const int a_r = (lane & 7) + ((lane >> 3) & 1) * 8;
    const int a_c = (lane >> 4) * 8;
    const int b_r = (lane & 7) + (lane >> 4) * 8;
    const int b_c = ((lane >> 3) & 1) * 8;

    const uint32_t tQ = sbase;
    const uint32_t tK = sbase + ST_ELEMS * 2;

    CP_WAIT(0);
    __syncthreads();

    #pragma unroll
    for (int ks = 0; ks < 4; ks++) {
        uint32_t ah[2][4], bhf[16];
        #pragma unroll
        for (int mi = 0; mi < 2; mi++) {
            uint32_t off = (uint32_t)((wm + mi * 16 + a_r) * SP + ks * 16 + a_c) * 2;
            ldm_x4(tQ + off, ah[mi]);
        }
        #pragma unroll
        for (int nj2 = 0; nj2 < 4; nj2++) {
            uint32_t off = (uint32_t)((wn + nj2 * 16 + b_r) * SP + ks * 16 + b_c) * 2;
            ldm_x4(tK + off, bhf + nj2 * 4);
        }
        #pragma unroll
        for (int mi = 0; mi < 2; mi++)
            #pragma unroll
            for (int nj = 0; nj < 8; nj++)
                mma_f16(acc[mi][nj], ah[mi], bhf + nj * 2);
    }

    const int group = lane >> 2, tid4 = lane & 3;
    float mq[4];
    #pragma unroll
    for (int mi = 0; mi < 2; mi++) {
        mq[mi * 2 + 0] = mask[b * SEQ + bm + wm + mi * 16 + group];
        mq[mi * 2 + 1] = mask[b * SEQ + bm + wm + mi * 16 + group + 8];
    }
    __half* out = e16 + (size_t)bh * SEQ * SEQ;
    float srow[2][2];
    srow[0][0] = srow[0][1] = srow[1][0] = srow[1][1] = 0.0f;
    #pragma unroll
    for (int nj = 0; nj < 8; nj++) {
        int cc = bn + wn + nj * 8 + tid4 * 2;
        float2 mk = *(const float2*)(mask + b * SEQ + cc);
        #pragma unroll
        for (int mi = 0; mi < 2; mi++) {
            int r0 = bm + wm + mi * 16 + group;
            float v0 = acc[mi][nj][0], v1 = acc[mi][nj][1];
            float v2 = acc[mi][nj][2], v3 = acc[mi][nj][3];
            if (mq[mi * 2 + 0] * mk.x == 0.0f) v0 = -100000.0f;
            if (mq[mi * 2 + 0] * mk.y == 0.0f) v1 = -100000.0f;
            if (mq[mi * 2 + 1] * mk.x == 0.0f) v2 = -100000.0f;
            if (mq[mi * 2 + 1] * mk.y == 0.0f) v3 = -100000.0f;
            __half h0 = __float2half_rn(fmaxf(fexp(v0 * 0.03125f), 1e-7f));
            __half h1 = __float2half_rn(fmaxf(fexp(v1 * 0.03125f), 1e-7f));
            __half h2 = __float2half_rn(fmaxf(fexp(v2 * 0.03125f), 1e-7f));
            __half h3 = __float2half_rn(fmaxf(fexp(v3 * 0.03125f), 1e-7f));
            __half2 p01; p01.x = h0; p01.y = h1;
            __half2 p23; p23.x = h2; p23.y = h3;
            *(__half2*)(out + (size_t)r0 * SEQ + cc) = p01;
            *(__half2*)(out + (size_t)(r0 + 8) * SEQ + cc) = p23;
            srow[mi][0] += __half2float(h0) + __half2float(h1);
            srow[mi][1] += __half2float(h2) + __half2float(h3);
        }
    }
    #pragma unroll
    for (int mi = 0; mi < 2; mi++) {
        #pragma unroll
        for (int s = 0; s < 2; s++) {
            srow[mi][s] += __shfl_xor_sync(0xffffffffu, srow[mi][s], 1);
            srow[mi][s] += __shfl_xor_sync(0xffffffffu, srow[mi][s], 2);
        }
    }
    __syncthreads();
    float* rs = (float*)smh;
    if (tid4 == 0) {
        #pragma unroll
        for (int mi = 0; mi < 2; mi++) {
            rs[(wm + mi * 16 + group) * 2 + (warp & 1)] = srow[mi][0];
            rs[(wm + mi * 16 + group + 8) * 2 + (warp & 1)] = srow[mi][1];
        }
    }
    __syncthreads();
    if (t < 128)
        psum[((size_t)bh * SEQ + bm + t) * 16 + blockIdx.x] = rs[t * 2] + rs[t * 2 + 1];
}

// ---------------------------------------------------------------------------
// av v3: 64-row q-tiles (grid x2), fused rowinv, plain stores.
// Warps: 8 = 4 row-groups x 2 N-halves (16 rows x 32 cols each).
// SMEM: E 2x[64][72]h | V 2x[64][72]h | inv[64]  (~37 KB)
// ---------------------------------------------------------------------------
#define EP 72
#define AVE(i) ((i) * 9216)
#define AVV(i) (18432 + (i) * 9216)
#define AVINV  36864
#define SMEM_AV (36864 + 256)

__global__ __launch_bounds__(256) void av_mma_kernel(
    const __half* __restrict__ e16, float* __restrict__ attn,
    const __half* __restrict__ q16,
    __half* __restrict__ aohi, __half* __restrict__ aolo,
    const float* __restrict__ psum)
{
    extern __shared__ char smc[];
    const uint32_t sbase = smem_u32(smc);
    const int t = threadIdx.x;
    const int warp = t >> 5, lane = t & 31;
    const int bh = blockIdx.y;
    const int b = bh / HEADS, h = bh % HEADS;
    const int bm = blockIdx.x * 64;
    const int wm = (warp & 3) * 16;        // row group within 64
    const int wn2 = (warp >> 2) * 32;      // N half (0 or 32)

    const __half* Ebase = e16 + (size_t)bh * SEQ * SEQ + (size_t)bm * SEQ;
    float* Abase = attn + (size_t)bh * SEQ * SEQ + (size_t)bm * SEQ;
    const __half* V = q16 + (size_t)b * SEQ * D3 + 2 * D_MODEL + h * HD;

    float* inv_s = (float*)(smc + AVINV);
    if (t < 64) {
        const float* p = psum + ((size_t)bh * SEQ + bm + t) * 16;
        float4 a = *(const float4*)(p);
        float4 b2 = *(const float4*)(p + 4);
        float4 cc = *(const float4*)(p + 8);
        float4 d = *(const float4*)(p + 12);
        float s = a.x + a.y + a.z + a.w + b2.x + b2.y + b2.z + b2.w
                + cc.x + cc.y + cc.z + cc.w + d.x + d.y + d.z + d.w;
        inv_s[t] = 1.0f / s;
    }
    __syncthreads();

    auto load_chunk = [&](int c) {
        const int k0 = c * 64;
        const uint32_t buf = c & 1;
        #pragma unroll
        for (int i = 0; i < 2; i++) {          // E: 64 rows x 8 segs = 512
            int id = t + i * 256;
            int r = id >> 3, cs = id & 7;
            cp_async16(sbase + AVE(buf) + (uint32_t)(r * EP + cs * 8) * 2,
                       Ebase + (size_t)r * SEQ + k0 + cs * 8);
        }
        #pragma unroll
        for (int i = 0; i < 2; i++) {          // V: 64 rows x 8 segs = 512
            int id = t + i * 256;
            int r = id >> 3, cs = id & 7;
            cp_async16(sbase + AVV(buf) + (uint32_t)(r * EP + cs * 8) * 2,
                       V + (size_t)(k0 + r) * D3 + cs * 8);
        }
        CP_COMMIT();
    };

    float acc[4][4];
    #pragma unroll
    for (int nj = 0; nj < 4; nj++)
        #pragma unroll
        for (int e = 0; e < 4; e++) acc[nj][e] = 0.0f;

    load_chunk(0);

    const int a_r = (lane & 7) + ((lane >> 3) & 1) * 8;
    const int a_c = (lane >> 4) * 8;
    const int tb_r = lane & 15;
    const int tb_c = (lane >> 4) * 8;

    for (int c = 0; c < SEQ / 64; c++) {
        CP_WAIT(0);
        __syncthreads();
        const int k0 = c * 64;
        const uint32_t buf = c & 1;
        if (c + 1 < SEQ / 64) load_chunk(c + 1);

        // normalized fp32 attn write-back: 64 rows x 16 float4 = 1024
        const __half* Es = (const __half*)(smc + AVE(buf));
        #pragma unroll
        for (int i = 0; i < 4; i++) {
            int id = t + i * 256;
            int r = id >> 4, c4 = id & 15;
            uint2 raw = *(const uint2*)(Es + r * EP + c4 * 4);
            __half2 p01 = *(__half2*)&raw.x;
            __half2 p23 = *(__half2*)&raw.y;
            float s = inv_s[r];
            float4 o;
            o.x = __half2float(p01.x) * s;
            o.y = __half2float(p01.y) * s;
            o.z = __half2float(p23.x) * s;
            o.w = __half2float(p23.y) * s;
            *(float4*)(Abase + (size_t)r * SEQ + k0 + c4 * 4) = o;
        }

        const uint32_t tA = sbase + AVE(buf);
        const uint32_t tV = sbase + AVV(buf);
        #pragma unroll
        for (int ks = 0; ks < 4; ks++) {
            uint32_t ah[4], bhf[8];
            uint32_t aoff = (uint32_t)((wm + a_r) * EP + ks * 16 + a_c) * 2;
            ldm_x4(tA + aoff, ah);
            #pragma unroll
            for (int nj2 = 0; nj2 < 2; nj2++) {
                uint32_t boff =
                    (uint32_t)((ks * 16 + tb_r) * EP + wn2 + nj2 * 16 + tb_c) * 2;
                ldm_x4_trans(tV + boff, bhf + nj2 * 4);
            }
            #pragma unroll
            for (int nj = 0; nj < 4; nj++)
                mma_f16(acc[nj], ah, bhf + nj * 2);
        }
    }

    const int group = lane >> 2, tid4 = lane & 3;
    const float ia = inv_s[wm + group];
    const float ib = inv_s[wm + group + 8];
    #pragma unroll
    for (int nj = 0; nj < 4; nj++) {
        int cc = h * HD + wn2 + nj * 8 + tid4 * 2;
        size_t r0 = (size_t)(b * SEQ + bm + wm + group) * D_MODEL + cc;
        size_t r1 = r0 + (size_t)8 * D_MODEL;
        split_store2_h(aohi, aolo, r0, acc[nj][0] * ia, acc[nj][1] * ia);
        split_store2_h(aohi, aolo, r1, acc[nj][2] * ib, acc[nj][3] * ib);
    }
}

// ---------------------------------------------------------------------------
extern "C" void kernel_launch(void* const* d_in, const int* in_sizes, int n_in,
                              void* d_out, int out_size)
{
    const float* x     = (const float*)d_in[0];
    const float* mask  = (const float*)d_in[1];
    const float* W_qkv = (const float*)d_in[2];
    const float* W_h   = (const float*)d_in[3];
    const float* b_h   = (const float*)d_in[4];

    float* out  = (float*)d_out;
    float* attn = out + (size_t)BL * D_MODEL;

    __half *x16, *wq16, *wh16, *q16, *e16, *aohi, *aolo;
    float *psum;
    cudaGetSymbolAddress((void**)&x16, g_x16);
    cudaGetSymbolAddress((void**)&wq16, g_wq16);
    cudaGetSymbolAddress((void**)&wh16, g_wh16);
    cudaGetSymbolAddress((void**)&q16, g_q16);
    cudaGetSymbolAddress((void**)&aohi, g_ao16h);
    cudaGetSymbolAddress((void**)&aolo, g_ao16l);
    cudaGetSymbolAddress((void**)&psum, g_psum);
    cudaGetSymbolAddress((void**)&e16, g_e16);

    cudaFuncSetAttribute(qkv_gemm_f16_kernel, cudaFuncAttributeMaxDynamicSharedMemorySize, SMEM_QKV);
    cudaFuncSetAttribute(outproj_gemm_f16_kernel, cudaFuncAttributeMaxDynamicSharedMemorySize, SMEM_OP);
    cudaFuncSetAttribute(scores_mma_kernel, cudaFuncAttributeMaxDynamicSharedMemorySize, SMEM_SCORES);
    cudaFuncSetAttribute(av_mma_kernel, cudaFuncAttributeMaxDynamicSharedMemorySize, SMEM_AV);

    // 0) fused input conversions
    convert_all_kernel<<<4096 + 3072 + 1024, 256>>>(x, x16, W_qkv, wq16, W_h, wh16);

    // 1) QKV = x @ W_qkv (fp16 1-term, BK=64, 3-stage) -> fp16
    qkv_gemm_f16_kernel<<<dim3(D3 / 128, BL / 128), 256, SMEM_QKV>>>(
        x16, wq16, q16, BL, D3, D_MODEL);

    // 2) scores (fp16 1-term) + fused exp -> fp16 scratch + psums
    scores_mma_kernel<<<dim3(SEQ / 128, SEQ / 128, BATCH * HEADS), 256, SMEM_SCORES>>>(
        mask, e16, q16, psum);

    // 3) attn @ V (64-row tiles, fused rowinv) + normalized fp32 attn write
    av_mma_kernel<<<dim3(SEQ / 64, BATCH * HEADS), 256, SMEM_AV>>>(
        e16, attn, q16, aohi, aolo, psum);

    // 4) output = ao @ W_h + b_h (fp16 2-term)
    outproj_gemm_f16_kernel<<<dim3(D_MODEL / 128, BL / 128), 256, SMEM_OP>>>(
        aohi, aolo, wh16, out, b_h, BL, D_MODEL, D_MODEL);
}

// round 17
// speedup vs baseline: 1.0530x; 1.0349x over previous
#include <cuda_runtime.h>
#include <cuda_bf16.h>
#include <cuda_fp16.h>
#include <math.h>
#include <stdint.h>

#define D_MODEL 1024
#define HEADS 16
#define HD 64
#define BATCH 2
#define SEQ 2048
#define BL (BATCH * SEQ)      /* 4096 */
#define D3 (3 * D_MODEL)      /* 3072 */
#define NROWS (BATCH * HEADS * SEQ)

typedef __nv_bfloat16 bf16;

// ---------------------------------------------------------------------------
// Scratch (allocation-free: __device__ globals)
// ---------------------------------------------------------------------------
__device__ __half g_x16[(size_t)BL * D_MODEL];
__device__ __half g_wq16[(size_t)D3 * D_MODEL];
__device__ __half g_wh16[(size_t)D_MODEL * D_MODEL];
__device__ __half g_q16[(size_t)BL * D3];        // QKV fp16
__device__ __half g_ao16h[(size_t)BL * D_MODEL]; // attn_out fp16 hi
__device__ __half g_ao16l[(size_t)BL * D_MODEL]; // attn_out fp16 lo
__device__ float g_psum[(size_t)NROWS * 16];
__device__ __half g_e16[(size_t)NROWS * SEQ];    // unnormalized exp, fp16

// ---------------------------------------------------------------------------
// Portable PTX helpers
// ---------------------------------------------------------------------------
__device__ __forceinline__ uint32_t smem_u32(const void* p) {
    uint32_t a;
    asm("{ .reg .u64 t; cvta.to.shared.u64 t, %1; cvt.u32.u64 %0, t; }"
        : "=r"(a) : "l"(p));
    return a;
}
__device__ __forceinline__ void cp_async16(uint32_t s, const void* g) {
    asm volatile("cp.async.cg.shared.global [%0], [%1], 16;" :: "r"(s), "l"(g));
}
#define CP_COMMIT() asm volatile("cp.async.commit_group;" ::: "memory")
#define CP_WAIT(n)  asm volatile("cp.async.wait_group %0;" :: "n"(n) : "memory")

__device__ __forceinline__ void ldm_x4(uint32_t addr, uint32_t* r) {
    asm volatile("ldmatrix.sync.aligned.m8n8.x4.shared.b16 {%0,%1,%2,%3}, [%4];"
        : "=r"(r[0]), "=r"(r[1]), "=r"(r[2]), "=r"(r[3]) : "r"(addr));
}
__device__ __forceinline__ void ldm_x4_trans(uint32_t addr, uint32_t* r) {
    asm volatile("ldmatrix.sync.aligned.m8n8.x4.trans.shared.b16 {%0,%1,%2,%3}, [%4];"
        : "=r"(r[0]), "=r"(r[1]), "=r"(r[2]), "=r"(r[3]) : "r"(addr));
}
__device__ __forceinline__ void mma_f16(float* c, const uint32_t* a, const uint32_t* b) {
    asm volatile(
        "mma.sync.aligned.m16n8k16.row.col.f32.f16.f16.f32 "
        "{%0,%1,%2,%3}, {%4,%5,%6,%7}, {%8,%9}, {%0,%1,%2,%3};"
        : "+f"(c[0]), "+f"(c[1]), "+f"(c[2]), "+f"(c[3])
        : "r"(a[0]), "r"(a[1]), "r"(a[2]), "r"(a[3]), "r"(b[0]), "r"(b[1]));
}
__device__ __forceinline__ void split_store2_h(__half* hi, __half* lo, size_t idx,
                                               float a, float b) {
    __half ha = __float2half_rn(a), hb = __float2half_rn(b);
    __half la = __float2half_rn(a - __half2float(ha));
    __half lb = __float2half_rn(b - __half2float(hb));
    __half2 hv; hv.x = ha; hv.y = hb;
    __half2 lv; lv.x = la; lv.y = lb;
    *(__half2*)(hi + idx) = hv;
    *(__half2*)(lo + idx) = lv;
}
__device__ __forceinline__ float fexp(float x) {
    float t = x * 1.4426950408889634f;
    t = fmaxf(t, -126.0f);
    float n = rintf(t);
    float f = t - n;
    float p = 1.5403530e-4f;
    p = fmaf(p, f, 1.3333558e-3f);
    p = fmaf(p, f, 9.6181291e-3f);
    p = fmaf(p, f, 5.5504109e-2f);
    p = fmaf(p, f, 2.4022651e-1f);
    p = fmaf(p, f, 6.9314718e-1f);
    p = fmaf(p, f, 1.0f);
    return p * __int_as_float(((int)n + 127) << 23);
}

// ---------------------------------------------------------------------------
// Fused conversion kernel (R15-proven layout).
// ---------------------------------------------------------------------------
__global__ __launch_bounds__(256) void convert_all_kernel(
    const float* __restrict__ x, __half* __restrict__ x16,
    const float* __restrict__ Wq, __half* __restrict__ wq16,
    const float* __restrict__ Wh, __half* __restrict__ wh16)
{
    const int bx = blockIdx.x;
    if (bx < 4096) {
        int i = bx * 256 + threadIdx.x;
        float4 v = ((const float4*)x)[i];
        __half h[4];
        h[0] = __float2half_rn(v.x);
        h[1] = __float2half_rn(v.y);
        h[2] = __float2half_rn(v.z);
        h[3] = __float2half_rn(v.w);
        ((uint2*)x16)[i] = *(uint2*)h;
        return;
    }
    __shared__ float tile[32][33];
    const float* W;
    __half* O;
    int nx, ky, K, N;
    if (bx < 4096 + 3072) {
        int id = bx - 4096;
        W = Wq; O = wq16; K = D_MODEL; N = D3;
        nx = (id % 96) * 32; ky = (id / 96) * 32;
    } else {
        int id = bx - 7168;
        W = Wh; O = wh16; K = D_MODEL; N = D_MODEL;
        nx = (id % 32) * 32; ky = (id / 32) * 32;
    }
    const int tx = threadIdx.x & 31;
    const int ty = threadIdx.x >> 5;
    #pragma unroll
    for (int i = 0; i < 4; i++)
        tile[ty + 8 * i][tx] = W[(size_t)(ky + ty + 8 * i) * N + nx + tx];
    __syncthreads();
    #pragma unroll
    for (int i = 0; i < 4; i++) {
        float v = tile[tx][ty + 8 * i];
        O[(size_t)(nx + ty + 8 * i) * K + ky + tx] = __float2half_rn(v);
    }
}

// ---------------------------------------------------------------------------
// fp16 1-term QKV GEMM: C = A @ B^T, fp16 out. BK=64, 3-stage pipeline.
// ---------------------------------------------------------------------------
#define QBK 64
#define QGP 72
#define QT_ELEMS (128 * QGP)
#define QS_ELEMS (2 * QT_ELEMS)
#define SMEM_QKV (3 * QS_ELEMS * 2)

__global__ __launch_bounds__(256, 2) void qkv_gemm_f16_kernel(
    const __half* __restrict__ A, const __half* __restrict__ B,
    __half* __restrict__ C, int M, int N, int K)
{
    extern __shared__ __half smq[];
    const uint32_t sbase = smem_u32(smq);
    const int t = threadIdx.x;
    const int warp = t >> 5, lane = t & 31;
    const int bm = blockIdx.y * 128;
    const int bn = blockIdx.x * 128;
    const int wm = (warp >> 1) * 32;
    const int wn = (warp & 1) * 64;

    const __half* srcs[2] = { A, B };

    auto load_stage = [&](int buf, int k0) {
        uint32_t sdst = sbase + (uint32_t)buf * QS_ELEMS * 2;
        #pragma unroll
        for (int m = 0; m < 2; m++) {
            const int rbase = (m == 0) ? bm : bn;
            const __half* S = srcs[m] + (size_t)rbase * K + k0;
            uint32_t td = sdst + (uint32_t)m * QT_ELEMS * 2;
            #pragma unroll
            for (int i = 0; i < 4; i++) {
                int id = t + i * 256;
                int row = id >> 3, c = id & 7;
                cp_async16(td + (uint32_t)(row * QGP + c * 8) * 2,
                           S + (size_t)row * K + c * 8);
            }
        }
        CP_COMMIT();
    };

    float acc[2][8][4];
    #pragma unroll
    for (int mi = 0; mi < 2; mi++)
        #pragma unroll
        for (int nj = 0; nj < 8; nj++)
            #pragma unroll
            for (int e = 0; e < 4; e++) acc[mi][nj][e] = 0.0f;

    const int nch = K >> 6;
    load_stage(0, 0);
    load_stage(1, QBK);

    const int a_r = (lane & 7) + ((lane >> 3) & 1) * 8;
    const int a_c = (lane >> 4) * 8;
    const int b_r = (lane & 7) + (lane >> 4) * 8;
    const int b_c = ((lane >> 3) & 1) * 8;

    int buf = 0;
    for (int c = 0; c < nch; c++) {
        CP_WAIT(1);
        __syncthreads();

        const uint32_t stg = sbase + (uint32_t)buf * QS_ELEMS * 2;
        const uint32_t tA = stg;
        const uint32_t tB = stg + QT_ELEMS * 2;

        #pragma unroll
        for (int ks = 0; ks < QBK; ks += 16) {
            uint32_t ah[2][4], bh[16];
            #pragma unroll
            for (int mi = 0; mi < 2; mi++) {
                uint32_t off = (uint32_t)((wm + mi * 16 + a_r) * QGP + ks + a_c) * 2;
                ldm_x4(tA + off, ah[mi]);
            }
            #pragma unroll
            for (int nj2 = 0; nj2 < 4; nj2++) {
                uint32_t off = (uint32_t)((wn + nj2 * 16 + b_r) * QGP + ks + b_c) * 2;
                ldm_x4(tB + off, bh + nj2 * 4);
            }
            #pragma unroll
            for (int mi = 0; mi < 2; mi++)
                #pragma unroll
                for (int nj = 0; nj < 8; nj++)
                    mma_f16(acc[mi][nj], ah[mi], bh + nj * 2);
        }
        __syncthreads();
        if (c + 2 < nch) {
            int nb = buf + 2;
            if (nb >= 3) nb -= 3;
            load_stage(nb, (c + 2) * QBK);
        } else {
            CP_COMMIT();
        }
        buf = (buf + 1 == 3) ? 0 : buf + 1;
    }

    const int group = lane >> 2, tid4 = lane & 3;
    #pragma unroll
    for (int mi = 0; mi < 2; mi++) {
        int r0 = bm + wm + mi * 16 + group;
        #pragma unroll
        for (int nj = 0; nj < 8; nj++) {
            int cc = bn + wn + nj * 8 + tid4 * 2;
            __half2 v0; v0.x = __float2half_rn(acc[mi][nj][0]);
            v0.y = __float2half_rn(acc[mi][nj][1]);
            __half2 v1; v1.x = __float2half_rn(acc[mi][nj][2]);
            v1.y = __float2half_rn(acc[mi][nj][3]);
            *(__half2*)(C + (size_t)r0 * N + cc) = v0;
            *(__half2*)(C + (size_t)(r0 + 8) * N + cc) = v1;
        }
    }
}

// ---------------------------------------------------------------------------
// fp16 2-term out-proj GEMM (R12-proven, plain stores).
// ---------------------------------------------------------------------------
#define BK 32
#define GP 40
#define GT_ELEMS (128 * GP)
#define OS_ELEMS (3 * GT_ELEMS)
#define SMEM_OP (2 * OS_ELEMS * 2)

__global__ __launch_bounds__(256, 2) void outproj_gemm_f16_kernel(
    const __half* __restrict__ Ahi, const __half* __restrict__ Alo,
    const __half* __restrict__ B, float* __restrict__ C,
    const float* __restrict__ bias, int M, int N, int K)
{
    extern __shared__ __half smq[];
    const uint32_t sbase = smem_u32(smq);
    const int t = threadIdx.x;
    const int warp = t >> 5, lane = t & 31;
    const int bm = blockIdx.y * 128;
    const int bn = blockIdx.x * 128;
    const int wm = (warp >> 1) * 32;
    const int wn = (warp & 1) * 64;

    const __half* srcs[3] = { Ahi, Alo, B };

    auto load_stage = [&](int buf, int k0) {
        uint32_t sdst = sbase + (uint32_t)buf * OS_ELEMS * 2;
        #pragma unroll
        for (int m = 0; m < 3; m++) {
            const int rbase = (m < 2) ? bm : bn;
            const __half* S = srcs[m] + (size_t)rbase * K + k0;
            uint32_t td = sdst + (uint32_t)m * GT_ELEMS * 2;
            #pragma unroll
            for (int i = 0; i < 2; i++) {
                int id = t + i * 256;
                int row = id >> 2, c = id & 3;
                cp_async16(td + (uint32_t)(row * GP + c * 8) * 2,
                           S + (size_t)row * K + c * 8);
            }
        }
        CP_COMMIT();
    };

    float acc[2][8][4];
    #pragma unroll
    for (int mi = 0; mi < 2; mi++)
        #pragma unroll
        for (int nj = 0; nj < 8; nj++)
            #pragma unroll
            for (int e = 0; e < 4; e++) acc[mi][nj][e] = 0.0f;

    const int nch = K >> 5;
    load_stage(0, 0);
    load_stage(1, BK);

    const int a_r = (lane & 7) + ((lane >> 3) & 1) * 8;
    const int a_c = (lane >> 4) * 8;
    const int b_r = (lane & 7) + (lane >> 4) * 8;
    const int b_c = ((lane >> 3) & 1) * 8;

    for (int c = 0; c < nch; c++) {
        if (c < nch - 1) { CP_WAIT(1); } else { CP_WAIT(0); }
        __syncthreads();

        const uint32_t stg = sbase + (uint32_t)(c & 1) * OS_ELEMS * 2;
        const uint32_t tAhi = stg;
        const uint32_t tAlo = stg + GT_ELEMS * 2;
        const uint32_t tB = stg + 2 * GT_ELEMS * 2;

        #pragma unroll
        for (int ks = 0; ks < BK; ks += 16) {
            uint32_t ah[2][4], al[2][4], bh[16];
            #pragma unroll
            for (int mi = 0; mi < 2; mi++) {
                uint32_t off = (uint32_t)((wm + mi * 16 + a_r) * GP + ks + a_c) * 2;
                ldm_x4(tAhi + off, ah[mi]);
                ldm_x4(tAlo + off, al[mi]);
            }
            #pragma unroll
            for (int nj2 = 0; nj2 < 4; nj2++) {
                uint32_t off = (uint32_t)((wn + nj2 * 16 + b_r) * GP + ks + b_c) * 2;
                ldm_x4(tB + off, bh + nj2 * 4);
            }
            #pragma unroll
            for (int mi = 0; mi < 2; mi++)
                #pragma unroll
                for (int nj = 0; nj < 8; nj++) {
                    mma_f16(acc[mi][nj], ah[mi], bh + nj * 2);
                    mma_f16(acc[mi][nj], al[mi], bh + nj * 2);
                }
        }
        __syncthreads();
        if (c + 2 < nch) load_stage(c & 1, (c + 2) * BK);
    }

    const int group = lane >> 2, tid4 = lane & 3;
    #pragma unroll
    for (int mi = 0; mi < 2; mi++) {
        int r0 = bm + wm + mi * 16 + group;
        #pragma unroll
        for (int nj = 0; nj < 8; nj++) {
            int cc = bn + wn + nj * 8 + tid4 * 2;
            float2 bb = *(const float2*)(bias + cc);
            *(float2*)(C + (size_t)r0 * N + cc) =
                make_float2(acc[mi][nj][0] + bb.x, acc[mi][nj][1] + bb.y);
            *(float2*)(C + (size_t)(r0 + 8) * N + cc) =
                make_float2(acc[mi][nj][2] + bb.x, acc[mi][nj][3] + bb.y);
        }
    }
}

// ---------------------------------------------------------------------------
// Scores via fp16 HMMA 1-term (R11-proven).
// ---------------------------------------------------------------------------
#define SP 72
#define ST_ELEMS (128 * SP)
#define SMEM_SCORES (2 * ST_ELEMS * 2)

__global__ __launch_bounds__(256, 2) void scores_mma_kernel(
    const float* __restrict__ mask, __half* __restrict__ e16,
    const __half* __restrict__ q16, float* __restrict__ psum)
{
    extern __shared__ __half smh[];
    const uint32_t sbase = smem_u32(smh);
    const int t = threadIdx.x;
    const int warp = t >> 5, lane = t & 31;
    const int bh = blockIdx.z;
    const int b = bh / HEADS, h = bh % HEADS;
    const int bm = blockIdx.y * 128;
    const int bn = blockIdx.x * 128;
    const int wm = (warp >> 1) * 32;
    const int wn = (warp & 1) * 64;

    const __half* bases[2] = {
        q16 + ((size_t)(b * SEQ + bm)) * D3 + h * HD,
        q16 + ((size_t)(b * SEQ + bn)) * D3 + D_MODEL + h * HD };
    #pragma unroll
    for (int m = 0; m < 2; m++) {
        uint32_t td = sbase + (uint32_t)m * ST_ELEMS * 2;
        #pragma unroll
        for (int i = 0; i < 4; i++) {
            int id = t + i * 256;
            int r = id >> 3, c = id & 7;
            cp_async16(td + (uint32_t)(r * SP + c * 8) * 2,
                       bases[m] + (size_t)r * D3 + c * 8);
        }
    }
    CP_COMMIT();

    float acc[2][8][4];
    #pragma unroll
    for (int mi = 0; mi < 2; mi++)
        #pragma unroll
        for (int nj = 0; nj < 8; nj++)
            #pragma unroll
            for (int e = 0; e < 4; e++) acc[mi][nj][e] = 0.0f;

    const int a_r = (lane & 7) + ((lane >> 3) & 1) * 8;
    const int a_c = (lane >> 4) * 8;
    const int b_r = (lane & 7) + (lane >> 4) * 8;
    const int b_c = ((lane >> 3) & 1) * 8;

    const uint32_t tQ = sbase;
    const uint32_t tK = sbase + ST_ELEMS * 2;

    CP_WAIT(0);
    __syncthreads();

    #pragma unroll
    for (int ks = 0; ks < 4; ks++) {
        uint32_t ah[2][4], bhf[16];
        #pragma unroll
        for (int mi = 0; mi < 2; mi++) {
            uint32_t off = (uint32_t)((wm + mi * 16 + a_r) * SP + ks * 16 + a_c) * 2;
            ldm_x4(tQ + off, ah[mi]);
        }
        #pragma unroll
        for (int nj2 = 0; nj2 < 4; nj2++) {
            uint32_t off = (uint32_t)((wn + nj2 * 16 + b_r) * SP + ks * 16 + b_c) * 2;
            ldm_x4(tK + off, bhf + nj2 * 4);
        }
        #pragma unroll
        for (int mi = 0; mi < 2; mi++)
            #pragma unroll
            for (int nj = 0; nj < 8; nj++)
                mma_f16(acc[mi][nj], ah[mi], bhf + nj * 2);
    }

    const int group = lane >> 2, tid4 = lane & 3;
    float mq[4];
    #pragma unroll
    for (int mi = 0; mi < 2; mi++) {
        mq[mi * 2 + 0] = mask[b * SEQ + bm + wm + mi * 16 + group];
        mq[mi * 2 + 1] = mask[b * SEQ + bm + wm + mi * 16 + group + 8];
    }
    __half* out = e16 + (size_t)bh * SEQ * SEQ;
    float srow[2][2];
    srow[0][0] = srow[0][1] = srow[1][0] = srow[1][1] = 0.0f;
    #pragma unroll
    for (int nj = 0; nj < 8; nj++) {
        int cc = bn + wn + nj * 8 + tid4 * 2;
        float2 mk = *(const float2*)(mask + b * SEQ + cc);
        #pragma unroll
        for (int mi = 0; mi < 2; mi++) {
            int r0 = bm + wm + mi * 16 + group;
            float v0 = acc[mi][nj][0], v1 = acc[mi][nj][1];
            float v2 = acc[mi][nj][2], v3 = acc[mi][nj][3];
            if (mq[mi * 2 + 0] * mk.x == 0.0f) v0 = -100000.0f;
            if (mq[mi * 2 + 0] * mk.y == 0.0f) v1 = -100000.0f;
            if (mq[mi * 2 + 1] * mk.x == 0.0f) v2 = -100000.0f;
            if (mq[mi * 2 + 1] * mk.y == 0.0f) v3 = -100000.0f;
            __half h0 = __float2half_rn(fmaxf(fexp(v0 * 0.03125f), 1e-7f));
            __half h1 = __float2half_rn(fmaxf(fexp(v1 * 0.03125f), 1e-7f));
            __half h2 = __float2half_rn(fmaxf(fexp(v2 * 0.03125f), 1e-7f));
            __half h3 = __float2half_rn(fmaxf(fexp(v3 * 0.03125f), 1e-7f));
            __half2 p01; p01.x = h0; p01.y = h1;
            __half2 p23; p23.x = h2; p23.y = h3;
            *(__half2*)(out + (size_t)r0 * SEQ + cc) = p01;
            *(__half2*)(out + (size_t)(r0 + 8) * SEQ + cc) = p23;
            srow[mi][0] += __half2float(h0) + __half2float(h1);
            srow[mi][1] += __half2float(h2) + __half2float(h3);
        }
    }
    #pragma unroll
    for (int mi = 0; mi < 2; mi++) {
        #pragma unroll
        for (int s = 0; s < 2; s++) {
            srow[mi][s] += __shfl_xor_sync(0xffffffffu, srow[mi][s], 1);
            srow[mi][s] += __shfl_xor_sync(0xffffffffu, srow[mi][s], 2);
        }
    }
    __syncthreads();
    float* rs = (float*)smh;
    if (tid4 == 0) {
        #pragma unroll
        for (int mi = 0; mi < 2; mi++) {
            rs[(wm + mi * 16 + group) * 2 + (warp & 1)] = srow[mi][0];
            rs[(wm + mi * 16 + group + 8) * 2 + (warp & 1)] = srow[mi][1];
        }
    }
    __syncthreads();
    if (t < 128)
        psum[((size_t)bh * SEQ + bm + t) * 16 + blockIdx.x] = rs[t * 2] + rs[t * 2 + 1];
}

// ---------------------------------------------------------------------------
// av v4: 64-row q-tiles, fused rowinv, 3-stage cp.async pipeline.
// SMEM: 3 stages x (E [64][72]h + V [64][72]h) + inv[64]  (~55.5 KB)
// ---------------------------------------------------------------------------
#define EP 72
#define AVSTG 18432
#define AVE(i) ((i) * AVSTG)
#define AVV(i) ((i) * AVSTG + 9216)
#define AVINV  (3 * AVSTG)
#define SMEM_AV (3 * AVSTG + 256)

__global__ __launch_bounds__(256) void av_mma_kernel(
    const __half* __restrict__ e16, float* __restrict__ attn,
    const __half* __restrict__ q16,
    __half* __restrict__ aohi, __half* __restrict__ aolo,
    const float* __restrict__ psum)
{
    extern __shared__ char smc[];
    const uint32_t sbase = smem_u32(smc);
    const int t = threadIdx.x;
    const int warp = t >> 5, lane = t & 31;
    const int bh = blockIdx.y;
    const int b = bh / HEADS, h = bh % HEADS;
    const int bm = blockIdx.x * 64;
    const int wm = (warp & 3) * 16;
    const int wn2 = (warp >> 2) * 32;

    const __half* Ebase = e16 + (size_t)bh * SEQ * SEQ + (size_t)bm * SEQ;
    float* Abase = attn + (size_t)bh * SEQ * SEQ + (size_t)bm * SEQ;
    const __half* V = q16 + (size_t)b * SEQ * D3 + 2 * D_MODEL + h * HD;

    float* inv_s = (float*)(smc + AVINV);
    if (t < 64) {
        const float* p = psum + ((size_t)bh * SEQ + bm + t) * 16;
        float4 a = *(const float4*)(p);
        float4 b2 = *(const float4*)(p + 4);
        float4 cc = *(const float4*)(p + 8);
        float4 d = *(const float4*)(p + 12);
        float s = a.x + a.y + a.z + a.w + b2.x + b2.y + b2.z + b2.w
                + cc.x + cc.y + cc.z + cc.w + d.x + d.y + d.z + d.w;
        inv_s[t] = 1.0f / s;
    }
    __syncthreads();

    auto load_chunk = [&](int buf, int c) {
        const int k0 = c * 64;
        #pragma unroll
        for (int i = 0; i < 2; i++) {
            int id = t + i * 256;
            int r = id >> 3, cs = id & 7;
            cp_async16(sbase + AVE(buf) + (uint32_t)(r * EP + cs * 8) * 2,
                       Ebase + (size_t)r * SEQ + k0 + cs * 8);
        }
        #pragma unroll
        for (int i = 0; i < 2; i++) {
            int id = t + i * 256;
            int r = id >> 3, cs = id & 7;
            cp_async16(sbase + AVV(buf) + (uint32_t)(r * EP + cs * 8) * 2,
                       V + (size_t)(k0 + r) * D3 + cs * 8);
        }
        CP_COMMIT();
    };

    float acc[4][4];
    #pragma unroll
    for (int nj = 0; nj < 4; nj++)
        #pragma unroll
        for (int e = 0; e < 4; e++) acc[nj][e] = 0.0f;

    const int nch = SEQ / 64;
    load_chunk(0, 0);
    load_chunk(1, 1);

    const int a_r = (lane & 7) + ((lane >> 3) & 1) * 8;
    const int a_c = (lane >> 4) * 8;
    const int tb_r = lane & 15;
    const int tb_c = (lane >> 4) * 8;

    int buf = 0;
    for (int c = 0; c < nch; c++) {
        CP_WAIT(1);
        __syncthreads();
        const int k0 = c * 64;
        if (c + 2 < nch) {
            int nb = buf + 2;
            if (nb >= 3) nb -= 3;
            load_chunk(nb, c + 2);
        } else {
            CP_COMMIT();
        }

        const __half* Es = (const __half*)(smc + AVE(buf));
        #pragma unroll
        for (int i = 0; i < 4; i++) {
            int id = t + i * 256;
            int r = id >> 4, c4 = id & 15;
            uint2 raw = *(const uint2*)(Es + r * EP + c4 * 4);
            __half2 p01 = *(__half2*)&raw.x;
            __half2 p23 = *(__half2*)&raw.y;
            float s = inv_s[r];
            float4 o;
            o.x = __half2float(p01.x) * s;
            o.y = __half2float(p01.y) * s;
            o.z = __half2float(p23.x) * s;
            o.w = __half2float(p23.y) * s;
            *(float4*)(Abase + (size_t)r * SEQ + k0 + c4 * 4) = o;
        }

        const uint32_t tA = sbase + AVE(buf);
        const uint32_t tV = sbase + AVV(buf);
        #pragma unroll
        for (int ks = 0; ks < 4; ks++) {
            uint32_t ah[4], bhf[8];
            uint32_t aoff = (uint32_t)((wm + a_r) * EP + ks * 16 + a_c) * 2;
            ldm_x4(tA + aoff, ah);
            #pragma unroll
            for (int nj2 = 0; nj2 < 2; nj2++) {
                uint32_t boff =
                    (uint32_t)((ks * 16 + tb_r) * EP + wn2 + nj2 * 16 + tb_c) * 2;
                ldm_x4_trans(tV + boff, bhf + nj2 * 4);
            }
            #pragma unroll
            for (int nj = 0; nj < 4; nj++)
                mma_f16(acc[nj], ah, bhf + nj * 2);
        }
        buf = (buf + 1 == 3) ? 0 : buf + 1;
    }

    const int group = lane >> 2, tid4 = lane & 3;
    const float ia = inv_s[wm + group];
    const float ib = inv_s[wm + group + 8];
    #pragma unroll
    for (int nj = 0; nj < 4; nj++) {
        int cc = h * HD + wn2 + nj * 8 + tid4 * 2;
        size_t r0 = (size_t)(b * SEQ + bm + wm + group) * D_MODEL + cc;
        size_t r1 = r0 + (size_t)8 * D_MODEL;
        split_store2_h(aohi, aolo, r0, acc[nj][0] * ia, acc[nj][1] * ia);
        split_store2_h(aohi, aolo, r1, acc[nj][2] * ib, acc[nj][3] * ib);
    }
}

// ---------------------------------------------------------------------------
extern "C" void kernel_launch(void* const* d_in, const int* in_sizes, int n_in,
                              void* d_out, int out_size)
{
    const float* x     = (const float*)d_in[0];
    const float* mask  = (const float*)d_in[1];
    const float* W_qkv = (const float*)d_in[2];
    const float* W_h   = (const float*)d_in[3];
    const float* b_h   = (const float*)d_in[4];

    float* out  = (float*)d_out;
    float* attn = out + (size_t)BL * D_MODEL;

    __half *x16, *wq16, *wh16, *q16, *e16, *aohi, *aolo;
    float *psum;
    cudaGetSymbolAddress((void**)&x16, g_x16);
    cudaGetSymbolAddress((void**)&wq16, g_wq16);
    cudaGetSymbolAddress((void**)&wh16, g_wh16);
    cudaGetSymbolAddress((void**)&q16, g_q16);
    cudaGetSymbolAddress((void**)&aohi, g_ao16h);
    cudaGetSymbolAddress((void**)&aolo, g_ao16l);
    cudaGetSymbolAddress((void**)&psum, g_psum);
    cudaGetSymbolAddress((void**)&e16, g_e16);

    cudaFuncSetAttribute(qkv_gemm_f16_kernel, cudaFuncAttributeMaxDynamicSharedMemorySize, SMEM_QKV);
    cudaFuncSetAttribute(outproj_gemm_f16_kernel, cudaFuncAttributeMaxDynamicSharedMemorySize, SMEM_OP);
    cudaFuncSetAttribute(scores_mma_kernel, cudaFuncAttributeMaxDynamicSharedMemorySize, SMEM_SCORES);
    cudaFuncSetAttribute(av_mma_kernel, cudaFuncAttributeMaxDynamicSharedMemorySize, SMEM_AV);

    // 0) fused input conversions
    convert_all_kernel<<<4096 + 3072 + 1024, 256>>>(x, x16, W_qkv, wq16, W_h, wh16);

    // 1) QKV = x @ W_qkv (fp16 1-term, BK=64, 3-stage) -> fp16
    qkv_gemm_f16_kernel<<<dim3(D3 / 128, BL / 128), 256, SMEM_QKV>>>(
        x16, wq16, q16, BL, D3, D_MODEL);

    // 2) scores (fp16 1-term) + fused exp -> fp16 scratch + psums
    scores_mma_kernel<<<dim3(SEQ / 128, SEQ / 128, BATCH * HEADS), 256, SMEM_SCORES>>>(
        mask, e16, q16, psum);

    // 3) attn @ V (64-row tiles, fused rowinv, 3-stage) + fp32 attn write
    av_mma_kernel<<<dim3(SEQ / 64, BATCH * HEADS), 256, SMEM_AV>>>(
        e16, attn, q16, aohi, aolo, psum);

    // 4) output = ao @ W_h + b_h (fp16 2-term)
    outproj_gemm_f16_kernel<<<dim3(D_MODEL / 128, BL / 128), 256, SMEM_OP>>>(
        aohi, aolo, wh16, out, b_h, BL, D_MODEL, D_MODEL);
}